// round 13
// baseline (speedup 1.0000x reference)
#include <cuda_runtime.h>
#include <cuda.h>
#include <cuda_bf16.h>
#include <cstdint>
#include <dlfcn.h>

// Problem constants
#define BTOT   4096
#define DTOT   16384
#define KTOT   512
#define CCOLS  100
#define CP     104            // padded C (13 x n8)
#define EPSV   1e-4f

// Work decomposition
#define BM     128            // batch rows per x-row tile
#define BD     128            // keys per d-tile
#define NROWS  32             // BTOT/BM
#define ITEMS_PER_ROW 32      // DTOT/(4*BD)
#define NITEMS 1024           // NROWS * ITEMS_PER_ROW, item = 4 d-tiles
#define MAXSLOT 20            // slot pairs per row in g_part
#define THREADS 256           // 8 warps: wm(4) x wd(2), M32 x N64 each

// SMEM offsets (from 1024-aligned base)
#define XS_OFF 0              // 8 chunks x [128 rows x 128B] SW128   131072
#define KS_OFF 131072         // 3 ring buffers x 16KB                 49152
#define VS_OFF 180224         // 2 halves x [104 rows x 128B]          26624
#define KK_OFF 206848         // 128 floats                              512
#define MB_OFF 207360         // mbarriers: xs, ksf[3], vs, ksc[3], vsc
#define SMEM_BYTES (207440 + 1024)

// -------- device globals --------
__device__ __align__(128) __nv_bfloat16 g_xb[(size_t)BTOT * KTOT];
__device__ __align__(128) __nv_bfloat16 g_kb[(size_t)DTOT * KTOT];
__device__ __align__(128) __nv_bfloat16 g_vT[(size_t)CP * DTOT];   // vT[c][d]
__device__ __align__(128) float g_xx[BTOT];
__device__ __align__(128) float g_kk[DTOT];
__device__ __align__(128) float g_part[(size_t)NROWS * MAXSLOT * BM * CP];

// -------- span arithmetic (deterministic static partition) --------
static __device__ __forceinline__ int item_start(int k, int N) {
    int q = NITEMS / N, r = NITEMS % N;
    return k * q + (k < r ? k : r);
}
static __device__ __forceinline__ int cta_of_item(int j, int N) {
    int q = NITEMS / N, r = NITEMS % N;
    int thresh = r * (q + 1);
    return (j < thresh) ? j / (q + 1) : r + (j - thresh) / q;
}

// -------- helpers --------
static __device__ __forceinline__ uint32_t sw128(uint32_t off) {
    return off ^ ((off >> 3) & 0x70);
}
static __device__ __forceinline__ unsigned packbf(float lo, float hi) {
    unsigned r;
    asm("cvt.rn.bf16x2.f32 %0, %1, %2;" : "=r"(r) : "f"(hi), "f"(lo));
    return r;
}
static __device__ __forceinline__ float rcpa(float x) {
    float r; asm("rcp.approx.f32 %0, %1;" : "=f"(r) : "f"(x)); return r;
}
static __device__ __forceinline__ void mma16816(float (&c)[4],
        unsigned a0, unsigned a1, unsigned a2, unsigned a3,
        unsigned b0, unsigned b1) {
    asm volatile(
        "mma.sync.aligned.m16n8k16.row.col.f32.bf16.bf16.f32 "
        "{%0,%1,%2,%3}, {%4,%5,%6,%7}, {%8,%9}, {%0,%1,%2,%3};"
        : "+f"(c[0]), "+f"(c[1]), "+f"(c[2]), "+f"(c[3])
        : "r"(a0), "r"(a1), "r"(a2), "r"(a3), "r"(b0), "r"(b1));
}
static __device__ __forceinline__ void ldsm4(unsigned &r0, unsigned &r1,
        unsigned &r2, unsigned &r3, uint32_t addr) {
    asm volatile("ldmatrix.sync.aligned.m8n8.x4.shared.b16 {%0,%1,%2,%3}, [%4];"
        : "=r"(r0), "=r"(r1), "=r"(r2), "=r"(r3) : "r"(addr));
}
static __device__ __forceinline__ void ldsm2(unsigned &r0, unsigned &r1, uint32_t addr) {
    asm volatile("ldmatrix.sync.aligned.m8n8.x2.shared.b16 {%0,%1}, [%2];"
        : "=r"(r0), "=r"(r1) : "r"(addr));
}
static __device__ __forceinline__ void tma2d(uint32_t dst, const void* map,
                                             int cx, int cy, uint32_t mbar) {
    asm volatile(
        "cp.async.bulk.tensor.2d.shared::cluster.global.tile.mbarrier::complete_tx::bytes "
        "[%0], [%1, {%2, %3}], [%4];"
        :: "r"(dst), "l"(map), "r"(cx), "r"(cy), "r"(mbar) : "memory");
}
static __device__ __forceinline__ void bulk1d(uint32_t dst, const void* src,
                                              uint32_t bytes, uint32_t mbar) {
    asm volatile(
        "cp.async.bulk.shared::cluster.global.mbarrier::complete_tx::bytes "
        "[%0], [%1], %2, [%3];"
        :: "r"(dst), "l"(src), "r"(bytes), "r"(mbar) : "memory");
}
#define MB_INIT(mb, n) asm volatile("mbarrier.init.shared.b64 [%0], %1;" \
    :: "r"(mb), "r"((uint32_t)(n)) : "memory")
#define MB_EXPECT_TX(mb, tx) asm volatile( \
    "mbarrier.arrive.expect_tx.shared.b64 _, [%0], %1;" \
    :: "r"(mb), "r"((uint32_t)(tx)) : "memory")
#define MB_ARRIVE(mb) asm volatile("mbarrier.arrive.shared.b64 _, [%0];" \
    :: "r"(mb) : "memory")
static __device__ __forceinline__ void mb_wait(uint32_t mb, uint32_t parity) {
    asm volatile("{\n\t.reg .pred P1;\n\t"
        "WL_%=:\n\t"
        "mbarrier.try_wait.parity.acquire.cta.shared::cta.b64 P1, [%0], %1, 0x989680;\n\t"
        "@P1 bra.uni WD_%=;\n\t"
        "bra.uni WL_%=;\n\t"
        "WD_%=:\n\t}" :: "r"(mb), "r"(parity) : "memory");
}

// -------- prologue kernels --------
__global__ void prep_rows(const float* __restrict__ src,
                          __nv_bfloat16* __restrict__ dst,
                          float* __restrict__ sq) {
    const int r = blockIdx.x;
    const int tid = threadIdx.x;           // 128
    const float* row = src + (size_t)r * KTOT;
    __nv_bfloat16* drow = dst + (size_t)r * KTOT;
    float s = 0.f;
    #pragma unroll
    for (int c = tid; c < KTOT; c += 128) {
        float v = row[c];
        drow[c] = __float2bfloat16(v);
        s += v * v;
    }
    #pragma unroll
    for (int o = 16; o > 0; o >>= 1) s += __shfl_xor_sync(0xFFFFFFFFu, s, o);
    __shared__ float ws[4];
    if ((tid & 31) == 0) ws[tid >> 5] = s;
    __syncthreads();
    if (tid == 0) sq[r] = ws[0] + ws[1] + ws[2] + ws[3];
}

__global__ void prep_vT(const float* __restrict__ values) {
    const int n = CP * DTOT;
    for (int i = blockIdx.x * blockDim.x + threadIdx.x; i < n;
         i += gridDim.x * blockDim.x) {
        int c = i >> 14;          // / DTOT
        int d = i & (DTOT - 1);
        g_vT[i] = (c < CCOLS) ? __float2bfloat16(values[(size_t)d * CCOLS + c])
                              : __float2bfloat16(0.f);
    }
}

// -------- main fused persistent kernel --------
__global__ void __launch_bounds__(THREADS, 1)
varkeys_main(const __grid_constant__ CUtensorMap tmx,
             const __grid_constant__ CUtensorMap tmk,
             const __grid_constant__ CUtensorMap tmv) {
    extern __shared__ __align__(16) char smem_raw[];
    char* smb = (char*)((((uintptr_t)smem_raw) + 1023) & ~(uintptr_t)1023);
    uint32_t su;
    asm("{ .reg .u64 t; cvta.to.shared.u64 t, %1; cvt.u32.u64 %0, t; }"
        : "=r"(su) : "l"(smb));

    const int tid  = threadIdx.x;
    const int warp = tid >> 5;
    const int lane = tid & 31;
    const int g = lane >> 2;
    const int t = lane & 3;
    const int wm = warp & 3;       // M group: rows [wm*32, +32)
    const int wd = warp >> 2;      // key half: keys [wd*64, +64) of BD=128
    const int N  = gridDim.x;
    const int k  = blockIdx.x;

    const int ia = item_start(k, N);
    const int ib = item_start(k + 1, N);
    const int ntile = (ib - ia) * 4;

    const uint32_t mb_xs = su + MB_OFF;
    const uint32_t mb_ks = su + MB_OFF + 8;    // full[3]
    const uint32_t mb_vs = su + MB_OFF + 32;
    const uint32_t mb_kc = su + MB_OFF + 40;   // ks consumed[3], 8 arrivals
    const uint32_t mb_vc = su + MB_OFF + 64;   // vs consumed, 8 arrivals

    if (tid == 0) {
        MB_INIT(mb_xs, 1);
        #pragma unroll
        for (int p = 0; p < 3; ++p) MB_INIT(mb_ks + p * 8, 1);
        MB_INIT(mb_vs, 1);
        #pragma unroll
        for (int p = 0; p < 3; ++p) MB_INIT(mb_kc + p * 8, 8);
        MB_INIT(mb_vc, 8);
    }
    __syncthreads();

    // tile index -> d coordinate within full D
    auto tile_d = [&](int tt) {
        int gi = ia + (tt >> 2);
        return ((gi & 31) * 4 + (tt & 3)) * BD;
    };

    int cur_row = ia >> 5;        // x-row of first item

    if (tid == 0) {
        MB_EXPECT_TX(mb_xs, 131072);
        #pragma unroll
        for (int c = 0; c < 8; ++c)
            tma2d(su + XS_OFF + c * 16384, &tmx, c * 64, cur_row * BM, mb_xs);
        const int dd0 = tile_d(0);
        #pragma unroll
        for (int p = 0; p < 3; ++p) {
            MB_EXPECT_TX(mb_ks + p * 8, 16384);
            tma2d(su + KS_OFF + p * 16384, &tmk, p * 64, dd0, mb_ks + p * 8);
        }
        MB_EXPECT_TX(mb_vs, 26624 + 512);
        tma2d(su + VS_OFF,         &tmv, dd0,      0, mb_vs);
        tma2d(su + VS_OFF + 13312, &tmv, dd0 + 64, 0, mb_vs);
        bulk1d(su + KK_OFF, g_kk + dd0, 512, mb_vs);
    }

    // ---- per-lane ldmatrix offsets ----
    const int ar = (lane & 7) + ((lane >> 3) & 1) * 8;
    const int ak = (lane >> 4) & 1;
    const uint32_t aoff0 = (uint32_t)(wm * 4 + (ar >> 3)) * 1024u;
    uint32_t asw[4];
    #pragma unroll
    for (int kk2i = 0; kk2i < 4; ++kk2i)
        asw[kk2i] = sw128((uint32_t)((ar & 7) * 128 + kk2i * 32 + ak * 16));

    const int br = (lane & 7) + ((lane >> 4) & 1) * 8;
    const int bk = (lane >> 3) & 1;
    const uint32_t boff0 = (uint32_t)(wd * 8 + (br >> 3)) * 1024u;
    uint32_t bsw[4];
    #pragma unroll
    for (int kk2i = 0; kk2i < 4; ++kk2i)
        bsw[kk2i] = sw128((uint32_t)((br & 7) * 128 + kk2i * 32 + bk * 16));

    uint32_t voff[6];
    #pragma unroll
    for (int j2 = 0; j2 < 6; ++j2) voff[j2] = (uint32_t)(j2 * 2 + (br >> 3)) * 1024u;
    uint32_t vsw[4], v2sw[4];
    const int l15 = lane & 15;
    #pragma unroll
    for (int k2 = 0; k2 < 4; ++k2) {
        vsw[k2]  = sw128((uint32_t)((br & 7) * 128 + k2 * 32 + bk * 16));
        v2sw[k2] = sw128((uint32_t)((l15 & 7) * 128 + k2 * 32 + ((l15 >> 3) & 1) * 16));
    }

    float xxe0, xxe1, xxe2, xxe3;
    auto load_xx = [&](int row) {
        const int m0 = row * BM + wm * 32;
        xxe0 = g_xx[m0 + g]      + EPSV;
        xxe1 = g_xx[m0 + 8 + g]  + EPSV;
        xxe2 = g_xx[m0 + 16 + g] + EPSV;
        xxe3 = g_xx[m0 + 24 + g] + EPSV;
    };
    load_xx(cur_row);

    float oacc[2][13][4];
    #pragma unroll
    for (int mh = 0; mh < 2; ++mh)
        #pragma unroll
        for (int j = 0; j < 13; ++j)
            #pragma unroll
            for (int q = 0; q < 4; ++q) oacc[mh][j][q] = 0.f;

    // flush this warp's accumulators to slot-indexed partials
    auto flush = [&](int row) {
        const int k0 = cta_of_item(row * ITEMS_PER_ROW, N);
        const int slot = (k - k0) * 2 + wd;
        #pragma unroll
        for (int mh = 0; mh < 2; ++mh) {
            const int ml = wm * 32 + mh * 16 + g;
            float* p0 = g_part + (((size_t)(row * MAXSLOT + slot) * BM) + ml) * CP;
            float* p1 = p0 + 8 * CP;
            #pragma unroll
            for (int j = 0; j < 13; ++j) {
                const int c0 = j * 8 + 2 * t;
                *(float2*)(p0 + c0) = make_float2(oacc[mh][j][0], oacc[mh][j][1]);
                *(float2*)(p1 + c0) = make_float2(oacc[mh][j][2], oacc[mh][j][3]);
            }
        }
    };

    mb_wait(mb_xs, 0);
    uint32_t xs_par = 0;
    int gc = 0;                   // chunk counter over whole span

    #pragma unroll 1
    for (int tt = 0; tt < ntile; ++tt) {
        const int gi  = ia + (tt >> 2);
        const int row = gi >> 5;
        if (row != cur_row) {     // x-row switch: flush, reload xs
            flush(cur_row);
            #pragma unroll
            for (int mh = 0; mh < 2; ++mh)
                #pragma unroll
                for (int j = 0; j < 13; ++j)
                    #pragma unroll
                    for (int q = 0; q < 4; ++q) oacc[mh][j][q] = 0.f;
            __syncthreads();      // all warps done reading old xs
            xs_par ^= 1;
            if (tid == 0) {
                MB_EXPECT_TX(mb_xs, 131072);
                #pragma unroll
                for (int c = 0; c < 8; ++c)
                    tma2d(su + XS_OFF + c * 16384, &tmx, c * 64, row * BM, mb_xs);
            }
            mb_wait(mb_xs, xs_par);
            load_xx(row);
            cur_row = row;
        }

        float sacc[2][8][4];
        #pragma unroll
        for (int mh = 0; mh < 2; ++mh)
            #pragma unroll
            for (int nt = 0; nt < 8; ++nt)
                #pragma unroll
                for (int q = 0; q < 4; ++q) sacc[mh][nt][q] = 0.f;

        // ---- GEMM1: 8 chunks, ring-3, consumed-mbarrier gated refill ----
        #pragma unroll 1
        for (int c = 0; c < 8; ++c, ++gc) {
            const uint32_t bi  = (uint32_t)(gc % 3);
            const uint32_t par = (uint32_t)((gc / 3) & 1);
            mb_wait(mb_ks + bi * 8, par);

            const uint32_t ab = su + XS_OFF + (uint32_t)c * 16384 + aoff0;
            const uint32_t bb = su + KS_OFF + bi * 16384 + boff0;
            #pragma unroll
            for (int kst = 0; kst < 4; ++kst) {
                unsigned a0,a1,a2,a3, a4,a5,a6,a7;
                ldsm4(a0,a1,a2,a3, ab + asw[kst]);
                ldsm4(a4,a5,a6,a7, ab + 2048 + asw[kst]);
                #pragma unroll
                for (int j = 0; j < 4; ++j) {
                    unsigned b0,b1,b2,b3;
                    ldsm4(b0,b1,b2,b3, bb + (uint32_t)j * 2048 + bsw[kst]);
                    mma16816(sacc[0][2*j],   a0,a1,a2,a3, b0,b1);
                    mma16816(sacc[0][2*j+1], a0,a1,a2,a3, b2,b3);
                    mma16816(sacc[1][2*j],   a4,a5,a6,a7, b0,b1);
                    mma16816(sacc[1][2*j+1], a4,a5,a6,a7, b2,b3);
                }
            }
            if (lane == 0) MB_ARRIVE(mb_kc + bi * 8);   // this warp consumed bi
            const int gr = gc + 3;
            if (warp == 0 && lane == 0 && gr < ntile * 8) {
                mb_wait(mb_kc + bi * 8, par);           // all 8 warps consumed
                MB_EXPECT_TX(mb_ks + bi * 8, 16384);
                const int t2 = gr >> 3;
                tma2d(su + KS_OFF + bi * 16384, &tmk,
                      (gr & 7) * 64, tile_d(t2), mb_ks + bi * 8);
            }
        }

        // ---- epilogue interleaved with GEMM2, per k2-step ----
        // kern = 1/(xx+kk-2s+eps) -> bf16 A-frags, immediately consumed
        mb_wait(mb_vs, (uint32_t)(tt & 1));
        const float2* kk2 = (const float2*)(smb + KK_OFF);
        const uint32_t vb = su + VS_OFF + (uint32_t)wd * 13312;
        #pragma unroll
        for (int k2 = 0; k2 < 4; ++k2) {
            unsigned fa[2][4];
            #pragma unroll
            for (int h = 0; h < 2; ++h) {
                const int nt = 2 * k2 + h;
                float2 kv = kk2[wd * 32 + nt * 4 + t];
                fa[0][2*h]   = packbf(rcpa(fmaf(-2.f, sacc[0][nt][0], xxe0 + kv.x)),
                                      rcpa(fmaf(-2.f, sacc[0][nt][1], xxe0 + kv.y)));
                fa[0][2*h+1] = packbf(rcpa(fmaf(-2.f, sacc[0][nt][2], xxe1 + kv.x)),
                                      rcpa(fmaf(-2.f, sacc[0][nt][3], xxe1 + kv.y)));
                fa[1][2*h]   = packbf(rcpa(fmaf(-2.f, sacc[1][nt][0], xxe2 + kv.x)),
                                      rcpa(fmaf(-2.f, sacc[1][nt][1], xxe2 + kv.y)));
                fa[1][2*h+1] = packbf(rcpa(fmaf(-2.f, sacc[1][nt][2], xxe3 + kv.x)),
                                      rcpa(fmaf(-2.f, sacc[1][nt][3], xxe3 + kv.y)));
            }
            #pragma unroll
            for (int j2 = 0; j2 < 6; ++j2) {
                unsigned b0,b1,b2,b3;
                ldsm4(b0,b1,b2,b3, vb + voff[j2] + vsw[k2]);
                #pragma unroll
                for (int mh = 0; mh < 2; ++mh) {
                    mma16816(oacc[mh][2*j2],   fa[mh][0], fa[mh][1],
                             fa[mh][2], fa[mh][3], b0, b1);
                    mma16816(oacc[mh][2*j2+1], fa[mh][0], fa[mh][1],
                             fa[mh][2], fa[mh][3], b2, b3);
                }
            }
            unsigned b0, b1;
            ldsm2(b0, b1, vb + 12288 + v2sw[k2]);
            #pragma unroll
            for (int mh = 0; mh < 2; ++mh)
                mma16816(oacc[mh][12], fa[mh][0], fa[mh][1],
                         fa[mh][2], fa[mh][3], b0, b1);
        }

        // vs/kk consumed by this warp (no block sync; producer gates refill)
        if (lane == 0) MB_ARRIVE(mb_vc);
        if (warp == 0 && lane == 0 && tt + 1 < ntile) {
            mb_wait(mb_vc, (uint32_t)(tt & 1));       // all 8 warps consumed
            const int dn = tile_d(tt + 1);
            MB_EXPECT_TX(mb_vs, 26624 + 512);
            tma2d(su + VS_OFF,         &tmv, dn,      0, mb_vs);
            tma2d(su + VS_OFF + 13312, &tmv, dn + 64, 0, mb_vs);
            bulk1d(su + KK_OFF, g_kk + dn, 512, mb_vs);
        }
    }

    flush(cur_row);
}

// -------- final reduce over slot partials --------
__global__ void reduce_out(float* __restrict__ out, int N) {
    int i = blockIdx.x * blockDim.x + threadIdx.x;
    if (i >= BTOT * CCOLS) return;
    const int m = i / CCOLS;
    const int c = i - m * CCOLS;
    const int row = m >> 7;
    const int mrow = m & 127;
    const int k0 = cta_of_item(row * ITEMS_PER_ROW, N);
    float s = 0.f;
    int sI = 0;
    while (k0 + sI < N && item_start(k0 + sI, N) < row * ITEMS_PER_ROW + ITEMS_PER_ROW) {
        const float* p = g_part + ((size_t)(row * MAXSLOT + 2 * sI) * BM + mrow) * CP + c;
        s += p[0] + p[(size_t)BM * CP];   // slot 2s and 2s+1 (wd halves)
        ++sI;
    }
    out[i] = s;
}

// -------- host --------
typedef CUresult (*PFN_tmEncode)(CUtensorMap*, CUtensorMapDataType, cuuint32_t,
    void*, const cuuint64_t*, const cuuint64_t*, const cuuint32_t*,
    const cuuint32_t*, CUtensorMapInterleave, CUtensorMapSwizzle,
    CUtensorMapL2promotion, CUtensorMapFloatOOBfill);

#ifndef RTLD_DEFAULT
#define RTLD_DEFAULT ((void*)0)
#endif

extern "C" void kernel_launch(void* const* d_in, const int* in_sizes, int n_in,
                              void* d_out, int out_size) {
    const float* x      = (const float*)d_in[0];   // (4096, 512)
    const float* keys   = (const float*)d_in[1];   // (16384, 512)
    const float* values = (const float*)d_in[2];   // (16384, 100)
    float* out = (float*)d_out;                    // (4096, 100)
    (void)in_sizes; (void)n_in; (void)out_size;

    void *xb_p, *kb_p, *vt_p, *xx_p, *kk_p;
    cudaGetSymbolAddress(&xb_p, g_xb);
    cudaGetSymbolAddress(&kb_p, g_kb);
    cudaGetSymbolAddress(&vt_p, g_vT);
    cudaGetSymbolAddress(&xx_p, g_xx);
    cudaGetSymbolAddress(&kk_p, g_kk);

    // Prologue
    prep_rows<<<BTOT, 128>>>(x, (__nv_bfloat16*)xb_p, (float*)xx_p);
    prep_rows<<<DTOT, 128>>>(keys, (__nv_bfloat16*)kb_p, (float*)kk_p);
    prep_vT<<<2048, 256>>>(values);

    // Tensor maps (driver API via dlsym; no -lcuda link dependency)
    void* fn = dlsym(RTLD_DEFAULT, "cuTensorMapEncodeTiled");
    if (!fn) {
        void* h = dlopen("libcuda.so.1", RTLD_NOW | RTLD_GLOBAL);
        if (h) fn = dlsym(h, "cuTensorMapEncodeTiled");
    }
    PFN_tmEncode enc = (PFN_tmEncode)fn;

    CUtensorMap tmx{}, tmk{}, tmv{};
    {
        cuuint64_t dims[2]    = {KTOT, BTOT};
        cuuint64_t strides[1] = {KTOT * 2};
        cuuint32_t box[2]     = {64, 128};
        cuuint32_t es[2]      = {1, 1};
        enc(&tmx, CU_TENSOR_MAP_DATA_TYPE_BFLOAT16, 2, xb_p, dims, strides, box, es,
            CU_TENSOR_MAP_INTERLEAVE_NONE, CU_TENSOR_MAP_SWIZZLE_128B,
            CU_TENSOR_MAP_L2_PROMOTION_L2_128B, CU_TENSOR_MAP_FLOAT_OOB_FILL_NONE);
    }
    {
        cuuint64_t dims[2]    = {KTOT, DTOT};
        cuuint64_t strides[1] = {KTOT * 2};
        cuuint32_t box[2]     = {64, 128};     // one TMA per 16KB ring buffer
        cuuint32_t es[2]      = {1, 1};
        enc(&tmk, CU_TENSOR_MAP_DATA_TYPE_BFLOAT16, 2, kb_p, dims, strides, box, es,
            CU_TENSOR_MAP_INTERLEAVE_NONE, CU_TENSOR_MAP_SWIZZLE_128B,
            CU_TENSOR_MAP_L2_PROMOTION_L2_128B, CU_TENSOR_MAP_FLOAT_OOB_FILL_NONE);
    }
    {
        cuuint64_t dims[2]    = {DTOT, CP};
        cuuint64_t strides[1] = {DTOT * 2};
        cuuint32_t box[2]     = {64, CP};
        cuuint32_t es[2]      = {1, 1};
        enc(&tmv, CU_TENSOR_MAP_DATA_TYPE_BFLOAT16, 2, vt_p, dims, strides, box, es,
            CU_TENSOR_MAP_INTERLEAVE_NONE, CU_TENSOR_MAP_SWIZZLE_128B,
            CU_TENSOR_MAP_L2_PROMOTION_L2_128B, CU_TENSOR_MAP_FLOAT_OOB_FILL_NONE);
    }

    // Persistent grid = #SMs (clamped so row-overlap fits MAXSLOT)
    int dev = 0, nsm = 128;
    cudaGetDevice(&dev);
    cudaDeviceGetAttribute(&nsm, cudaDevAttrMultiProcessorCount, dev);
    int N = nsm > 160 ? 160 : nsm;

    cudaFuncSetAttribute(varkeys_main,
                         cudaFuncAttributeMaxDynamicSharedMemorySize, SMEM_BYTES);
    varkeys_main<<<N, THREADS, SMEM_BYTES>>>(tmx, tmk, tmv);

    reduce_out<<<(BTOT * CCOLS + 255) / 256, 256>>>(out, N);
}

// round 14
// speedup vs baseline: 1.0595x; 1.0595x over previous
#include <cuda_runtime.h>
#include <cuda.h>
#include <cuda_bf16.h>
#include <cstdint>
#include <dlfcn.h>

// Problem constants
#define BTOT   4096
#define DTOT   16384
#define KTOT   512
#define CCOLS  100
#define CP     104            // padded C (13 x n8)
#define EPSV   1e-4f

// Work decomposition
#define BM     128            // batch rows per x-row tile
#define BD     128            // keys per d-tile
#define NROWS  32             // BTOT/BM
#define ITEMS_PER_ROW 32      // DTOT/(4*BD)
#define NITEMS 1024           // NROWS * ITEMS_PER_ROW, item = 4 d-tiles
#define MAXSLOT 20            // slot pairs per row in g_part
#define THREADS 256           // 8 warps: wm(4) x wd(2), M32 x N64 each

// SMEM offsets (from 1024-aligned base)
#define XS_OFF 0              // 8 chunks x [128 rows x 128B] SW128   131072
#define KS_OFF 131072         // 3 ring buffers x 16KB                 49152
#define VS_OFF 180224         // 2 halves x [104 rows x 128B]          26624
#define KK_OFF 206848         // 128 floats                              512
#define MB_OFF 207360         // mbarriers: xs, ksf[3], vs, ksc[3]
#define SMEM_BYTES (207424 + 1024)

// -------- device globals --------
__device__ __align__(128) __nv_bfloat16 g_xb[(size_t)BTOT * KTOT];
__device__ __align__(128) __nv_bfloat16 g_kb[(size_t)DTOT * KTOT];
__device__ __align__(128) __nv_bfloat16 g_vT[(size_t)CP * DTOT];   // vT[c][d]
__device__ __align__(128) float g_xx[BTOT];
__device__ __align__(128) float g_kk[DTOT];
__device__ __align__(128) float g_part[(size_t)NROWS * MAXSLOT * BM * CP];

// -------- span arithmetic (deterministic static partition) --------
static __device__ __forceinline__ int item_start(int k, int N) {
    int q = NITEMS / N, r = NITEMS % N;
    return k * q + (k < r ? k : r);
}
static __device__ __forceinline__ int cta_of_item(int j, int N) {
    int q = NITEMS / N, r = NITEMS % N;
    int thresh = r * (q + 1);
    return (j < thresh) ? j / (q + 1) : r + (j - thresh) / q;
}

// -------- helpers --------
static __device__ __forceinline__ uint32_t sw128(uint32_t off) {
    return off ^ ((off >> 3) & 0x70);
}
static __device__ __forceinline__ unsigned packbf(float lo, float hi) {
    unsigned r;
    asm("cvt.rn.bf16x2.f32 %0, %1, %2;" : "=r"(r) : "f"(hi), "f"(lo));
    return r;
}
static __device__ __forceinline__ float rcpa(float x) {
    float r; asm("rcp.approx.f32 %0, %1;" : "=f"(r) : "f"(x)); return r;
}
static __device__ __forceinline__ void mma16816(float (&c)[4],
        unsigned a0, unsigned a1, unsigned a2, unsigned a3,
        unsigned b0, unsigned b1) {
    asm volatile(
        "mma.sync.aligned.m16n8k16.row.col.f32.bf16.bf16.f32 "
        "{%0,%1,%2,%3}, {%4,%5,%6,%7}, {%8,%9}, {%0,%1,%2,%3};"
        : "+f"(c[0]), "+f"(c[1]), "+f"(c[2]), "+f"(c[3])
        : "r"(a0), "r"(a1), "r"(a2), "r"(a3), "r"(b0), "r"(b1));
}
static __device__ __forceinline__ void ldsm4(unsigned &r0, unsigned &r1,
        unsigned &r2, unsigned &r3, uint32_t addr) {
    asm volatile("ldmatrix.sync.aligned.m8n8.x4.shared.b16 {%0,%1,%2,%3}, [%4];"
        : "=r"(r0), "=r"(r1), "=r"(r2), "=r"(r3) : "r"(addr));
}
static __device__ __forceinline__ void ldsm2(unsigned &r0, unsigned &r1, uint32_t addr) {
    asm volatile("ldmatrix.sync.aligned.m8n8.x2.shared.b16 {%0,%1}, [%2];"
        : "=r"(r0), "=r"(r1) : "r"(addr));
}
static __device__ __forceinline__ void tma2d(uint32_t dst, const void* map,
                                             int cx, int cy, uint32_t mbar) {
    asm volatile(
        "cp.async.bulk.tensor.2d.shared::cluster.global.tile.mbarrier::complete_tx::bytes "
        "[%0], [%1, {%2, %3}], [%4];"
        :: "r"(dst), "l"(map), "r"(cx), "r"(cy), "r"(mbar) : "memory");
}
static __device__ __forceinline__ void bulk1d(uint32_t dst, const void* src,
                                              uint32_t bytes, uint32_t mbar) {
    asm volatile(
        "cp.async.bulk.shared::cluster.global.mbarrier::complete_tx::bytes "
        "[%0], [%1], %2, [%3];"
        :: "r"(dst), "l"(src), "r"(bytes), "r"(mbar) : "memory");
}
#define MB_INIT(mb, n) asm volatile("mbarrier.init.shared.b64 [%0], %1;" \
    :: "r"(mb), "r"((uint32_t)(n)) : "memory")
#define MB_EXPECT_TX(mb, tx) asm volatile( \
    "mbarrier.arrive.expect_tx.shared.b64 _, [%0], %1;" \
    :: "r"(mb), "r"((uint32_t)(tx)) : "memory")
#define MB_ARRIVE(mb) asm volatile("mbarrier.arrive.shared.b64 _, [%0];" \
    :: "r"(mb) : "memory")
static __device__ __forceinline__ void mb_wait(uint32_t mb, uint32_t parity) {
    asm volatile("{\n\t.reg .pred P1;\n\t"
        "WL_%=:\n\t"
        "mbarrier.try_wait.parity.acquire.cta.shared::cta.b64 P1, [%0], %1, 0x989680;\n\t"
        "@P1 bra.uni WD_%=;\n\t"
        "bra.uni WL_%=;\n\t"
        "WD_%=:\n\t}" :: "r"(mb), "r"(parity) : "memory");
}

// -------- prologue kernels --------
__global__ void prep_rows(const float* __restrict__ src,
                          __nv_bfloat16* __restrict__ dst,
                          float* __restrict__ sq) {
    const int r = blockIdx.x;
    const int tid = threadIdx.x;           // 128
    const float* row = src + (size_t)r * KTOT;
    __nv_bfloat16* drow = dst + (size_t)r * KTOT;
    float s = 0.f;
    #pragma unroll
    for (int c = tid; c < KTOT; c += 128) {
        float v = row[c];
        drow[c] = __float2bfloat16(v);
        s += v * v;
    }
    #pragma unroll
    for (int o = 16; o > 0; o >>= 1) s += __shfl_xor_sync(0xFFFFFFFFu, s, o);
    __shared__ float ws[4];
    if ((tid & 31) == 0) ws[tid >> 5] = s;
    __syncthreads();
    if (tid == 0) sq[r] = ws[0] + ws[1] + ws[2] + ws[3];
}

__global__ void prep_vT(const float* __restrict__ values) {
    const int n = CP * DTOT;
    for (int i = blockIdx.x * blockDim.x + threadIdx.x; i < n;
         i += gridDim.x * blockDim.x) {
        int c = i >> 14;          // / DTOT
        int d = i & (DTOT - 1);
        g_vT[i] = (c < CCOLS) ? __float2bfloat16(values[(size_t)d * CCOLS + c])
                              : __float2bfloat16(0.f);
    }
}

// -------- main fused persistent kernel --------
__global__ void __launch_bounds__(THREADS, 1)
varkeys_main(const __grid_constant__ CUtensorMap tmx,
             const __grid_constant__ CUtensorMap tmk,
             const __grid_constant__ CUtensorMap tmv) {
    extern __shared__ __align__(16) char smem_raw[];
    char* smb = (char*)((((uintptr_t)smem_raw) + 1023) & ~(uintptr_t)1023);
    uint32_t su;
    asm("{ .reg .u64 t; cvta.to.shared.u64 t, %1; cvt.u32.u64 %0, t; }"
        : "=r"(su) : "l"(smb));

    const int tid  = threadIdx.x;
    const int warp = tid >> 5;
    const int lane = tid & 31;
    const int g = lane >> 2;
    const int t = lane & 3;
    const int wm = warp & 3;       // M group: rows [wm*32, +32)
    const int wd = warp >> 2;      // key half: keys [wd*64, +64) of BD=128
    const int N  = gridDim.x;
    const int k  = blockIdx.x;

    const int ia = item_start(k, N);
    const int ib = item_start(k + 1, N);
    const int ntile = (ib - ia) * 4;

    const uint32_t mb_xs = su + MB_OFF;
    const uint32_t mb_ks = su + MB_OFF + 8;    // full[3]
    const uint32_t mb_vs = su + MB_OFF + 32;
    const uint32_t mb_kc = su + MB_OFF + 40;   // consumed[3], 8 arrivals

    if (tid == 0) {
        MB_INIT(mb_xs, 1);
        #pragma unroll
        for (int p = 0; p < 3; ++p) MB_INIT(mb_ks + p * 8, 1);
        MB_INIT(mb_vs, 1);
        #pragma unroll
        for (int p = 0; p < 3; ++p) MB_INIT(mb_kc + p * 8, 8);
    }
    __syncthreads();

    // tile index -> d coordinate within full D
    auto tile_d = [&](int tt) {
        int gi = ia + (tt >> 2);
        return ((gi & 31) * 4 + (tt & 3)) * BD;
    };

    int cur_row = ia >> 5;        // x-row of first item

    if (tid == 0) {
        // xs for first row
        MB_EXPECT_TX(mb_xs, 131072);
        #pragma unroll
        for (int c = 0; c < 8; ++c)
            tma2d(su + XS_OFF + c * 16384, &tmx, c * 64, cur_row * BM, mb_xs);
        // ks ring prefill: stream chunks 0,1,2 (tile 0 chunks 0..2)
        const int dd0 = tile_d(0);
        #pragma unroll
        for (int p = 0; p < 3; ++p) {
            MB_EXPECT_TX(mb_ks + p * 8, 16384);
            tma2d(su + KS_OFF + p * 16384, &tmk, p * 64, dd0, mb_ks + p * 8);
        }
        // vs + kk for tile 0
        MB_EXPECT_TX(mb_vs, 26624 + 512);
        tma2d(su + VS_OFF,         &tmv, dd0,      0, mb_vs);
        tma2d(su + VS_OFF + 13312, &tmv, dd0 + 64, 0, mb_vs);
        bulk1d(su + KK_OFF, g_kk + dd0, 512, mb_vs);
    }

    // ---- per-lane ldmatrix offsets ----
    const int ar = (lane & 7) + ((lane >> 3) & 1) * 8;
    const int ak = (lane >> 4) & 1;
    const uint32_t aoff0 = (uint32_t)(wm * 4 + (ar >> 3)) * 1024u;
    uint32_t asw[4];
    #pragma unroll
    for (int kk2i = 0; kk2i < 4; ++kk2i)
        asw[kk2i] = sw128((uint32_t)((ar & 7) * 128 + kk2i * 32 + ak * 16));

    const int br = (lane & 7) + ((lane >> 4) & 1) * 8;
    const int bk = (lane >> 3) & 1;
    const uint32_t boff0 = (uint32_t)(wd * 8 + (br >> 3)) * 1024u;
    uint32_t bsw[4];
    #pragma unroll
    for (int kk2i = 0; kk2i < 4; ++kk2i)
        bsw[kk2i] = sw128((uint32_t)((br & 7) * 128 + kk2i * 32 + bk * 16));

    uint32_t voff[6];
    #pragma unroll
    for (int j2 = 0; j2 < 6; ++j2) voff[j2] = (uint32_t)(j2 * 2 + (br >> 3)) * 1024u;
    uint32_t vsw[4], v2sw[4];
    const int l15 = lane & 15;
    #pragma unroll
    for (int k2 = 0; k2 < 4; ++k2) {
        vsw[k2]  = sw128((uint32_t)((br & 7) * 128 + k2 * 32 + bk * 16));
        v2sw[k2] = sw128((uint32_t)((l15 & 7) * 128 + k2 * 32 + ((l15 >> 3) & 1) * 16));
    }

    float xxe0, xxe1, xxe2, xxe3;
    auto load_xx = [&](int row) {
        const int m0 = row * BM + wm * 32;
        xxe0 = g_xx[m0 + g]      + EPSV;
        xxe1 = g_xx[m0 + 8 + g]  + EPSV;
        xxe2 = g_xx[m0 + 16 + g] + EPSV;
        xxe3 = g_xx[m0 + 24 + g] + EPSV;
    };
    load_xx(cur_row);

    float oacc[2][13][4];
    #pragma unroll
    for (int mh = 0; mh < 2; ++mh)
        #pragma unroll
        for (int j = 0; j < 13; ++j)
            #pragma unroll
            for (int q = 0; q < 4; ++q) oacc[mh][j][q] = 0.f;

    // flush this warp's accumulators to slot-indexed partials
    auto flush = [&](int row) {
        const int k0 = cta_of_item(row * ITEMS_PER_ROW, N);
        const int slot = (k - k0) * 2 + wd;
        #pragma unroll
        for (int mh = 0; mh < 2; ++mh) {
            const int ml = wm * 32 + mh * 16 + g;
            float* p0 = g_part + (((size_t)(row * MAXSLOT + slot) * BM) + ml) * CP;
            float* p1 = p0 + 8 * CP;
            #pragma unroll
            for (int j = 0; j < 13; ++j) {
                const int c0 = j * 8 + 2 * t;
                *(float2*)(p0 + c0) = make_float2(oacc[mh][j][0], oacc[mh][j][1]);
                *(float2*)(p1 + c0) = make_float2(oacc[mh][j][2], oacc[mh][j][3]);
            }
        }
    };

    mb_wait(mb_xs, 0);
    uint32_t xs_par = 0;
    int gc = 0;                   // chunk counter over whole span

    #pragma unroll 1
    for (int tt = 0; tt < ntile; ++tt) {
        const int gi  = ia + (tt >> 2);
        const int row = gi >> 5;
        if (row != cur_row) {     // x-row switch: flush, reload xs
            flush(cur_row);
            #pragma unroll
            for (int mh = 0; mh < 2; ++mh)
                #pragma unroll
                for (int j = 0; j < 13; ++j)
                    #pragma unroll
                    for (int q = 0; q < 4; ++q) oacc[mh][j][q] = 0.f;
            __syncthreads();      // all warps done reading old xs
            xs_par ^= 1;
            if (tid == 0) {
                MB_EXPECT_TX(mb_xs, 131072);
                #pragma unroll
                for (int c = 0; c < 8; ++c)
                    tma2d(su + XS_OFF + c * 16384, &tmx, c * 64, row * BM, mb_xs);
            }
            mb_wait(mb_xs, xs_par);
            load_xx(row);
            cur_row = row;
        }

        float sacc[2][8][4];
        #pragma unroll
        for (int mh = 0; mh < 2; ++mh)
            #pragma unroll
            for (int nt = 0; nt < 8; ++nt)
                #pragma unroll
                for (int q = 0; q < 4; ++q) sacc[mh][nt][q] = 0.f;

        // ---- GEMM1: 8 chunks, ring-3, consumed-mbarrier gated refill ----
        #pragma unroll 1
        for (int c = 0; c < 8; ++c, ++gc) {
            const uint32_t bi  = (uint32_t)(gc % 3);
            const uint32_t par = (uint32_t)((gc / 3) & 1);
            mb_wait(mb_ks + bi * 8, par);

            const uint32_t ab = su + XS_OFF + (uint32_t)c * 16384 + aoff0;
            const uint32_t bb = su + KS_OFF + bi * 16384 + boff0;
            #pragma unroll
            for (int kst = 0; kst < 4; ++kst) {
                unsigned a0,a1,a2,a3, a4,a5,a6,a7;
                ldsm4(a0,a1,a2,a3, ab + asw[kst]);
                ldsm4(a4,a5,a6,a7, ab + 2048 + asw[kst]);
                #pragma unroll
                for (int j = 0; j < 4; ++j) {
                    unsigned b0,b1,b2,b3;
                    ldsm4(b0,b1,b2,b3, bb + (uint32_t)j * 2048 + bsw[kst]);
                    mma16816(sacc[0][2*j],   a0,a1,a2,a3, b0,b1);
                    mma16816(sacc[0][2*j+1], a0,a1,a2,a3, b2,b3);
                    mma16816(sacc[1][2*j],   a4,a5,a6,a7, b0,b1);
                    mma16816(sacc[1][2*j+1], a4,a5,a6,a7, b2,b3);
                }
            }
            if (lane == 0) MB_ARRIVE(mb_kc + bi * 8);   // this warp consumed bi
            const int gr = gc + 3;
            if (warp == 0 && lane == 0 && gr < ntile * 8) {
                mb_wait(mb_kc + bi * 8, par);           // all 8 warps consumed
                MB_EXPECT_TX(mb_ks + bi * 8, 16384);
                const int t2 = gr >> 3;
                tma2d(su + KS_OFF + bi * 16384, &tmk,
                      (gr & 7) * 64, tile_d(t2), mb_ks + bi * 8);
            }
        }

        // ---- epilogue: kern = 1/(xx+kk-2s+eps) -> bf16 A-frags ----
        // quad-reciprocal: one MUFU rcp per 4 values (1/d from rcp(d0*d1*d2*d3))
        mb_wait(mb_vs, (uint32_t)(tt & 1));           // vs + kk ready
        const float2* kk2 = (const float2*)(smb + KK_OFF);
        unsigned apl[2][8], aph[2][8];
        #pragma unroll
        for (int nt = 0; nt < 8; ++nt) {
            float2 kv = kk2[wd * 32 + nt * 4 + t];
            #pragma unroll
            for (int mh = 0; mh < 2; ++mh) {
                const float xxa = (mh == 0) ? xxe0 : xxe2;
                const float xxb = (mh == 0) ? xxe1 : xxe3;
                float d0v = fmaf(-2.f, sacc[mh][nt][0], xxa + kv.x);
                float d1v = fmaf(-2.f, sacc[mh][nt][1], xxa + kv.y);
                float d2v = fmaf(-2.f, sacc[mh][nt][2], xxb + kv.x);
                float d3v = fmaf(-2.f, sacc[mh][nt][3], xxb + kv.y);
                float p01 = d0v * d1v;
                float p23 = d2v * d3v;
                float rr  = rcpa(p01 * p23);
                float r01 = rr * p23;      // 1/(d0*d1)
                float r23 = rr * p01;      // 1/(d2*d3)
                apl[mh][nt] = packbf(r01 * d1v, r01 * d0v);
                aph[mh][nt] = packbf(r23 * d3v, r23 * d2v);
            }
        }

        // ---- GEMM2: oacc[M32 x 104] += kern[M32 x k64(wd)] @ vT ----
        const uint32_t vb = su + VS_OFF + (uint32_t)wd * 13312;
        #pragma unroll
        for (int k2 = 0; k2 < 4; ++k2) {
            #pragma unroll
            for (int j2 = 0; j2 < 6; ++j2) {
                unsigned b0,b1,b2,b3;
                ldsm4(b0,b1,b2,b3, vb + voff[j2] + vsw[k2]);
                #pragma unroll
                for (int mh = 0; mh < 2; ++mh) {
                    mma16816(oacc[mh][2*j2],   apl[mh][2*k2], aph[mh][2*k2],
                             apl[mh][2*k2+1], aph[mh][2*k2+1], b0, b1);
                    mma16816(oacc[mh][2*j2+1], apl[mh][2*k2], aph[mh][2*k2],
                             apl[mh][2*k2+1], aph[mh][2*k2+1], b2, b3);
                }
            }
            unsigned b0, b1;
            ldsm2(b0, b1, vb + 12288 + v2sw[k2]);
            #pragma unroll
            for (int mh = 0; mh < 2; ++mh)
                mma16816(oacc[mh][12], apl[mh][2*k2], aph[mh][2*k2],
                         apl[mh][2*k2+1], aph[mh][2*k2+1], b0, b1);
        }

        __syncthreads();                              // vs/kk consumed by all
        if (tid == 0 && tt + 1 < ntile) {             // refill vs+kk for tt+1
            const int dn = tile_d(tt + 1);
            MB_EXPECT_TX(mb_vs, 26624 + 512);
            tma2d(su + VS_OFF,         &tmv, dn,      0, mb_vs);
            tma2d(su + VS_OFF + 13312, &tmv, dn + 64, 0, mb_vs);
            bulk1d(su + KK_OFF, g_kk + dn, 512, mb_vs);
        }
    }

    flush(cur_row);
}

// -------- final reduce over slot partials --------
__global__ void reduce_out(float* __restrict__ out, int N) {
    int i = blockIdx.x * blockDim.x + threadIdx.x;
    if (i >= BTOT * CCOLS) return;
    const int m = i / CCOLS;
    const int c = i - m * CCOLS;
    const int row = m >> 7;
    const int mrow = m & 127;
    const int k0 = cta_of_item(row * ITEMS_PER_ROW, N);
    float s = 0.f;
    int sI = 0;
    while (k0 + sI < N && item_start(k0 + sI, N) < row * ITEMS_PER_ROW + ITEMS_PER_ROW) {
        const float* p = g_part + ((size_t)(row * MAXSLOT + 2 * sI) * BM + mrow) * CP + c;
        s += p[0] + p[(size_t)BM * CP];   // slot 2s and 2s+1 (wd halves)
        ++sI;
    }
    out[i] = s;
}

// -------- host --------
typedef CUresult (*PFN_tmEncode)(CUtensorMap*, CUtensorMapDataType, cuuint32_t,
    void*, const cuuint64_t*, const cuuint64_t*, const cuuint32_t*,
    const cuuint32_t*, CUtensorMapInterleave, CUtensorMapSwizzle,
    CUtensorMapL2promotion, CUtensorMapFloatOOBfill);

#ifndef RTLD_DEFAULT
#define RTLD_DEFAULT ((void*)0)
#endif

extern "C" void kernel_launch(void* const* d_in, const int* in_sizes, int n_in,
                              void* d_out, int out_size) {
    const float* x      = (const float*)d_in[0];   // (4096, 512)
    const float* keys   = (const float*)d_in[1];   // (16384, 512)
    const float* values = (const float*)d_in[2];   // (16384, 100)
    float* out = (float*)d_out;                    // (4096, 100)
    (void)in_sizes; (void)n_in; (void)out_size;

    void *xb_p, *kb_p, *vt_p, *xx_p, *kk_p;
    cudaGetSymbolAddress(&xb_p, g_xb);
    cudaGetSymbolAddress(&kb_p, g_kb);
    cudaGetSymbolAddress(&vt_p, g_vT);
    cudaGetSymbolAddress(&xx_p, g_xx);
    cudaGetSymbolAddress(&kk_p, g_kk);

    // Prologue
    prep_rows<<<BTOT, 128>>>(x, (__nv_bfloat16*)xb_p, (float*)xx_p);
    prep_rows<<<DTOT, 128>>>(keys, (__nv_bfloat16*)kb_p, (float*)kk_p);
    prep_vT<<<2048, 256>>>(values);

    // Tensor maps (driver API via dlsym; no -lcuda link dependency)
    void* fn = dlsym(RTLD_DEFAULT, "cuTensorMapEncodeTiled");
    if (!fn) {
        void* h = dlopen("libcuda.so.1", RTLD_NOW | RTLD_GLOBAL);
        if (h) fn = dlsym(h, "cuTensorMapEncodeTiled");
    }
    PFN_tmEncode enc = (PFN_tmEncode)fn;

    CUtensorMap tmx{}, tmk{}, tmv{};
    {
        cuuint64_t dims[2]    = {KTOT, BTOT};
        cuuint64_t strides[1] = {KTOT * 2};
        cuuint32_t box[2]     = {64, 128};
        cuuint32_t es[2]      = {1, 1};
        enc(&tmx, CU_TENSOR_MAP_DATA_TYPE_BFLOAT16, 2, xb_p, dims, strides, box, es,
            CU_TENSOR_MAP_INTERLEAVE_NONE, CU_TENSOR_MAP_SWIZZLE_128B,
            CU_TENSOR_MAP_L2_PROMOTION_L2_128B, CU_TENSOR_MAP_FLOAT_OOB_FILL_NONE);
    }
    {
        cuuint64_t dims[2]    = {KTOT, DTOT};
        cuuint64_t strides[1] = {KTOT * 2};
        cuuint32_t box[2]     = {64, 128};     // one TMA per 16KB ring buffer
        cuuint32_t es[2]      = {1, 1};
        enc(&tmk, CU_TENSOR_MAP_DATA_TYPE_BFLOAT16, 2, kb_p, dims, strides, box, es,
            CU_TENSOR_MAP_INTERLEAVE_NONE, CU_TENSOR_MAP_SWIZZLE_128B,
            CU_TENSOR_MAP_L2_PROMOTION_L2_128B, CU_TENSOR_MAP_FLOAT_OOB_FILL_NONE);
    }
    {
        cuuint64_t dims[2]    = {DTOT, CP};
        cuuint64_t strides[1] = {DTOT * 2};
        cuuint32_t box[2]     = {64, CP};
        cuuint32_t es[2]      = {1, 1};
        enc(&tmv, CU_TENSOR_MAP_DATA_TYPE_BFLOAT16, 2, vt_p, dims, strides, box, es,
            CU_TENSOR_MAP_INTERLEAVE_NONE, CU_TENSOR_MAP_SWIZZLE_128B,
            CU_TENSOR_MAP_L2_PROMOTION_L2_128B, CU_TENSOR_MAP_FLOAT_OOB_FILL_NONE);
    }

    // Persistent grid = #SMs (clamped so row-overlap fits MAXSLOT)
    int dev = 0, nsm = 128;
    cudaGetDevice(&dev);
    cudaDeviceGetAttribute(&nsm, cudaDevAttrMultiProcessorCount, dev);
    int N = nsm > 160 ? 160 : nsm;

    cudaFuncSetAttribute(varkeys_main,
                         cudaFuncAttributeMaxDynamicSharedMemorySize, SMEM_BYTES);
    varkeys_main<<<N, THREADS, SMEM_BYTES>>>(tmx, tmk, tmv);

    reduce_out<<<(BTOT * CCOLS + 255) / 256, 256>>>(out, N);
}

// round 16
// speedup vs baseline: 1.0789x; 1.0184x over previous
#include <cuda_runtime.h>
#include <cuda.h>
#include <cuda_bf16.h>
#include <cstdint>
#include <dlfcn.h>

// Problem constants
#define BTOT   4096
#define DTOT   16384
#define KTOT   512
#define CCOLS  100
#define CP     104            // padded C (13 x n8)
#define EPSV   1e-4f

// Work decomposition
#define BM     128            // batch rows per x-row tile
#define BD     128            // keys per d-tile
#define NROWS  32             // BTOT/BM
#define ITEMS_PER_ROW 32      // DTOT/(4*BD)
#define NITEMS 1024           // NROWS * ITEMS_PER_ROW, item = 4 d-tiles
#define MAXSLOT 20            // slot pairs per row in g_part
#define THREADS 256           // 8 warps: wm(4) x wd(2), M32 x N64 each

// SMEM offsets (from 1024-aligned base)
#define XS_OFF 0              // 8 chunks x [128 rows x 128B] SW128   131072
#define KS_OFF 131072         // 3 ring buffers x 16KB                 49152
#define VS_OFF 180224         // 2 halves x [104 rows x 128B]          26624
#define KK_OFF 206848         // 128 floats                              512
#define MB_OFF 207360         // mbarriers: xs, ksf[3], vs, ksc[3], vsc
#define SMEM_BYTES (207440 + 1024)

// -------- device globals --------
__device__ __align__(128) __nv_bfloat16 g_xb[(size_t)BTOT * KTOT];
__device__ __align__(128) __nv_bfloat16 g_kb[(size_t)DTOT * KTOT];
__device__ __align__(128) __nv_bfloat16 g_vT[(size_t)CP * DTOT];   // vT[c][d]
__device__ __align__(128) float g_xx[BTOT];
__device__ __align__(128) float g_kk[DTOT];
__device__ __align__(128) float g_part[(size_t)NROWS * MAXSLOT * BM * CP];

// -------- span arithmetic (deterministic static partition) --------
static __device__ __forceinline__ int item_start(int k, int N) {
    int q = NITEMS / N, r = NITEMS % N;
    return k * q + (k < r ? k : r);
}
static __device__ __forceinline__ int cta_of_item(int j, int N) {
    int q = NITEMS / N, r = NITEMS % N;
    int thresh = r * (q + 1);
    return (j < thresh) ? j / (q + 1) : r + (j - thresh) / q;
}

// -------- helpers --------
static __device__ __forceinline__ uint32_t sw128(uint32_t off) {
    return off ^ ((off >> 3) & 0x70);
}
static __device__ __forceinline__ unsigned packbf(float lo, float hi) {
    unsigned r;
    asm("cvt.rn.bf16x2.f32 %0, %1, %2;" : "=r"(r) : "f"(hi), "f"(lo));
    return r;
}
static __device__ __forceinline__ float rcpa(float x) {
    float r; asm("rcp.approx.f32 %0, %1;" : "=f"(r) : "f"(x)); return r;
}
static __device__ __forceinline__ void mma16816(float (&c)[4],
        unsigned a0, unsigned a1, unsigned a2, unsigned a3,
        unsigned b0, unsigned b1) {
    asm volatile(
        "mma.sync.aligned.m16n8k16.row.col.f32.bf16.bf16.f32 "
        "{%0,%1,%2,%3}, {%4,%5,%6,%7}, {%8,%9}, {%0,%1,%2,%3};"
        : "+f"(c[0]), "+f"(c[1]), "+f"(c[2]), "+f"(c[3])
        : "r"(a0), "r"(a1), "r"(a2), "r"(a3), "r"(b0), "r"(b1));
}
static __device__ __forceinline__ void ldsm4(unsigned &r0, unsigned &r1,
        unsigned &r2, unsigned &r3, uint32_t addr) {
    asm volatile("ldmatrix.sync.aligned.m8n8.x4.shared.b16 {%0,%1,%2,%3}, [%4];"
        : "=r"(r0), "=r"(r1), "=r"(r2), "=r"(r3) : "r"(addr));
}
static __device__ __forceinline__ void ldsm2(unsigned &r0, unsigned &r1, uint32_t addr) {
    asm volatile("ldmatrix.sync.aligned.m8n8.x2.shared.b16 {%0,%1}, [%2];"
        : "=r"(r0), "=r"(r1) : "r"(addr));
}
static __device__ __forceinline__ void tma2d(uint32_t dst, const void* map,
                                             int cx, int cy, uint32_t mbar) {
    asm volatile(
        "cp.async.bulk.tensor.2d.shared::cluster.global.tile.mbarrier::complete_tx::bytes "
        "[%0], [%1, {%2, %3}], [%4];"
        :: "r"(dst), "l"(map), "r"(cx), "r"(cy), "r"(mbar) : "memory");
}
static __device__ __forceinline__ void bulk1d(uint32_t dst, const void* src,
                                              uint32_t bytes, uint32_t mbar) {
    asm volatile(
        "cp.async.bulk.shared::cluster.global.mbarrier::complete_tx::bytes "
        "[%0], [%1], %2, [%3];"
        :: "r"(dst), "l"(src), "r"(bytes), "r"(mbar) : "memory");
}
#define MB_INIT(mb, n) asm volatile("mbarrier.init.shared.b64 [%0], %1;" \
    :: "r"(mb), "r"((uint32_t)(n)) : "memory")
#define MB_EXPECT_TX(mb, tx) asm volatile( \
    "mbarrier.arrive.expect_tx.shared.b64 _, [%0], %1;" \
    :: "r"(mb), "r"((uint32_t)(tx)) : "memory")
#define MB_ARRIVE(mb) asm volatile("mbarrier.arrive.shared.b64 _, [%0];" \
    :: "r"(mb) : "memory")
static __device__ __forceinline__ void mb_wait(uint32_t mb, uint32_t parity) {
    asm volatile("{\n\t.reg .pred P1;\n\t"
        "WL_%=:\n\t"
        "mbarrier.try_wait.parity.acquire.cta.shared::cta.b64 P1, [%0], %1, 0x989680;\n\t"
        "@P1 bra.uni WD_%=;\n\t"
        "bra.uni WL_%=;\n\t"
        "WD_%=:\n\t}" :: "r"(mb), "r"(parity) : "memory");
}

// -------- prologue kernels --------
__global__ void prep_rows(const float* __restrict__ src,
                          __nv_bfloat16* __restrict__ dst,
                          float* __restrict__ sq) {
    const int r = blockIdx.x;
    const int tid = threadIdx.x;           // 128
    const float4* row = (const float4*)(src + (size_t)r * KTOT);
    uint2* drow = (uint2*)(dst + (size_t)r * KTOT);
    float4 v = row[tid];
    float s = v.x * v.x + v.y * v.y + v.z * v.z + v.w * v.w;
    uint2 o;
    o.x = packbf(v.x, v.y);
    o.y = packbf(v.z, v.w);
    drow[tid] = o;
    #pragma unroll
    for (int off = 16; off > 0; off >>= 1) s += __shfl_xor_sync(0xFFFFFFFFu, s, off);
    __shared__ float ws[4];
    if ((tid & 31) == 0) ws[tid >> 5] = s;
    __syncthreads();
    if (tid == 0) sq[r] = ws[0] + ws[1] + ws[2] + ws[3];
}

// transposed vT build via smem tile: coalesced read of values, coalesced write
__global__ void prep_vT(const float* __restrict__ values) {
    __shared__ __nv_bfloat16 tile[128][106];   // pitch 106: conflict-limited
    const int d0 = blockIdx.x * 128;
    const int tid = threadIdx.x;               // 256
    // load 128 rows x 100 cols (coalesced along c)
    for (int i = tid; i < 128 * CCOLS; i += 256) {
        int r = i / CCOLS, c = i - r * CCOLS;
        tile[r][c] = __float2bfloat16(values[(size_t)(d0 + r) * CCOLS + c]);
    }
    __syncthreads();
    // write CP x 128 transposed, packed as uints (coalesced along d)
    uint32_t* outw = (uint32_t*)g_vT;
    for (int i = tid; i < CP * 64; i += 256) {
        int c = i >> 6, p = i & 63;
        uint32_t w;
        if (c < CCOLS) {
            __nv_bfloat16 lo = tile[2 * p][c], hi = tile[2 * p + 1][c];
            w = (uint32_t)__bfloat16_as_ushort(lo)
              | ((uint32_t)__bfloat16_as_ushort(hi) << 16);
        } else w = 0u;
        outw[((size_t)c * DTOT + d0) / 2 + p] = w;
    }
}

// -------- main fused persistent kernel --------
__global__ void __launch_bounds__(THREADS, 1)
varkeys_main(const __grid_constant__ CUtensorMap tmx,
             const __grid_constant__ CUtensorMap tmk,
             const __grid_constant__ CUtensorMap tmv) {
    extern __shared__ __align__(16) char smem_raw[];
    char* smb = (char*)((((uintptr_t)smem_raw) + 1023) & ~(uintptr_t)1023);
    uint32_t su;
    asm("{ .reg .u64 t; cvta.to.shared.u64 t, %1; cvt.u32.u64 %0, t; }"
        : "=r"(su) : "l"(smb));

    const int tid  = threadIdx.x;
    const int warp = tid >> 5;
    const int lane = tid & 31;
    const int g = lane >> 2;
    const int t = lane & 3;
    const int wm = warp & 3;       // M group: rows [wm*32, +32)
    const int wd = warp >> 2;      // key half: keys [wd*64, +64) of BD=128
    const int N  = gridDim.x;
    const int k  = blockIdx.x;

    const int ia = item_start(k, N);
    const int ib = item_start(k + 1, N);
    const int ntile = (ib - ia) * 4;

    const uint32_t mb_xs = su + MB_OFF;
    const uint32_t mb_ks = su + MB_OFF + 8;    // full[3]
    const uint32_t mb_vs = su + MB_OFF + 32;
    const uint32_t mb_kc = su + MB_OFF + 40;   // ks consumed[3], 8 arrivals
    const uint32_t mb_vc = su + MB_OFF + 64;   // vs consumed, 8 arrivals

    if (tid == 0) {
        MB_INIT(mb_xs, 1);
        #pragma unroll
        for (int p = 0; p < 3; ++p) MB_INIT(mb_ks + p * 8, 1);
        MB_INIT(mb_vs, 1);
        #pragma unroll
        for (int p = 0; p < 3; ++p) MB_INIT(mb_kc + p * 8, 8);
        MB_INIT(mb_vc, 8);
    }
    __syncthreads();

    // tile index -> d coordinate within full D
    auto tile_d = [&](int tt) {
        int gi = ia + (tt >> 2);
        return ((gi & 31) * 4 + (tt & 3)) * BD;
    };

    int cur_row = ia >> 5;        // x-row of first item

    if (tid == 0) {
        // xs for first row
        MB_EXPECT_TX(mb_xs, 131072);
        #pragma unroll
        for (int c = 0; c < 8; ++c)
            tma2d(su + XS_OFF + c * 16384, &tmx, c * 64, cur_row * BM, mb_xs);
        // ks ring prefill: stream chunks 0,1,2 (tile 0 chunks 0..2)
        const int dd0 = tile_d(0);
        #pragma unroll
        for (int p = 0; p < 3; ++p) {
            MB_EXPECT_TX(mb_ks + p * 8, 16384);
            tma2d(su + KS_OFF + p * 16384, &tmk, p * 64, dd0, mb_ks + p * 8);
        }
        // vs + kk for tile 0
        MB_EXPECT_TX(mb_vs, 26624 + 512);
        tma2d(su + VS_OFF,         &tmv, dd0,      0, mb_vs);
        tma2d(su + VS_OFF + 13312, &tmv, dd0 + 64, 0, mb_vs);
        bulk1d(su + KK_OFF, g_kk + dd0, 512, mb_vs);
    }

    // ---- per-lane ldmatrix offsets ----
    const int ar = (lane & 7) + ((lane >> 3) & 1) * 8;
    const int ak = (lane >> 4) & 1;
    const uint32_t aoff0 = (uint32_t)(wm * 4 + (ar >> 3)) * 1024u;
    uint32_t asw[4];
    #pragma unroll
    for (int kk2i = 0; kk2i < 4; ++kk2i)
        asw[kk2i] = sw128((uint32_t)((ar & 7) * 128 + kk2i * 32 + ak * 16));

    const int br = (lane & 7) + ((lane >> 4) & 1) * 8;
    const int bk = (lane >> 3) & 1;
    const uint32_t boff0 = (uint32_t)(wd * 8 + (br >> 3)) * 1024u;
    uint32_t bsw[4];
    #pragma unroll
    for (int kk2i = 0; kk2i < 4; ++kk2i)
        bsw[kk2i] = sw128((uint32_t)((br & 7) * 128 + kk2i * 32 + bk * 16));

    uint32_t voff[6];
    #pragma unroll
    for (int j2 = 0; j2 < 6; ++j2) voff[j2] = (uint32_t)(j2 * 2 + (br >> 3)) * 1024u;
    uint32_t vsw[4], v2sw[4];
    const int l15 = lane & 15;
    #pragma unroll
    for (int k2 = 0; k2 < 4; ++k2) {
        vsw[k2]  = sw128((uint32_t)((br & 7) * 128 + k2 * 32 + bk * 16));
        v2sw[k2] = sw128((uint32_t)((l15 & 7) * 128 + k2 * 32 + ((l15 >> 3) & 1) * 16));
    }

    float xxe0, xxe1, xxe2, xxe3;
    auto load_xx = [&](int row) {
        const int m0 = row * BM + wm * 32;
        xxe0 = g_xx[m0 + g]      + EPSV;
        xxe1 = g_xx[m0 + 8 + g]  + EPSV;
        xxe2 = g_xx[m0 + 16 + g] + EPSV;
        xxe3 = g_xx[m0 + 24 + g] + EPSV;
    };
    load_xx(cur_row);

    float oacc[2][13][4];
    #pragma unroll
    for (int mh = 0; mh < 2; ++mh)
        #pragma unroll
        for (int j = 0; j < 13; ++j)
            #pragma unroll
            for (int q = 0; q < 4; ++q) oacc[mh][j][q] = 0.f;

    // flush this warp's accumulators to slot-indexed partials
    auto flush = [&](int row) {
        const int k0 = cta_of_item(row * ITEMS_PER_ROW, N);
        const int slot = (k - k0) * 2 + wd;
        #pragma unroll
        for (int mh = 0; mh < 2; ++mh) {
            const int ml = wm * 32 + mh * 16 + g;
            float* p0 = g_part + (((size_t)(row * MAXSLOT + slot) * BM) + ml) * CP;
            float* p1 = p0 + 8 * CP;
            #pragma unroll
            for (int j = 0; j < 13; ++j) {
                const int c0 = j * 8 + 2 * t;
                *(float2*)(p0 + c0) = make_float2(oacc[mh][j][0], oacc[mh][j][1]);
                *(float2*)(p1 + c0) = make_float2(oacc[mh][j][2], oacc[mh][j][3]);
            }
        }
    };

    mb_wait(mb_xs, 0);
    uint32_t xs_par = 0;
    int gc = 0;                   // chunk counter over whole span

    #pragma unroll 1
    for (int tt = 0; tt < ntile; ++tt) {
        const int gi  = ia + (tt >> 2);
        const int row = gi >> 5;
        if (row != cur_row) {     // x-row switch: flush, reload xs
            flush(cur_row);
            #pragma unroll
            for (int mh = 0; mh < 2; ++mh)
                #pragma unroll
                for (int j = 0; j < 13; ++j)
                    #pragma unroll
                    for (int q = 0; q < 4; ++q) oacc[mh][j][q] = 0.f;
            __syncthreads();      // all warps done reading old xs
            xs_par ^= 1;
            if (tid == 0) {
                MB_EXPECT_TX(mb_xs, 131072);
                #pragma unroll
                for (int c = 0; c < 8; ++c)
                    tma2d(su + XS_OFF + c * 16384, &tmx, c * 64, row * BM, mb_xs);
            }
            mb_wait(mb_xs, xs_par);
            load_xx(row);
            cur_row = row;
        }

        float sacc[2][8][4];
        #pragma unroll
        for (int mh = 0; mh < 2; ++mh)
            #pragma unroll
            for (int nt = 0; nt < 8; ++nt)
                #pragma unroll
                for (int q = 0; q < 4; ++q) sacc[mh][nt][q] = 0.f;

        // ---- GEMM1: 8 chunks, ring-3, consumed-mbarrier gated refill ----
        #pragma unroll 1
        for (int c = 0; c < 8; ++c, ++gc) {
            const uint32_t bi  = (uint32_t)(gc % 3);
            const uint32_t par = (uint32_t)((gc / 3) & 1);
            mb_wait(mb_ks + bi * 8, par);

            const uint32_t ab = su + XS_OFF + (uint32_t)c * 16384 + aoff0;
            const uint32_t bb = su + KS_OFF + bi * 16384 + boff0;
            #pragma unroll
            for (int kst = 0; kst < 4; ++kst) {
                unsigned a0,a1,a2,a3, a4,a5,a6,a7;
                ldsm4(a0,a1,a2,a3, ab + asw[kst]);
                ldsm4(a4,a5,a6,a7, ab + 2048 + asw[kst]);
                #pragma unroll
                for (int j = 0; j < 4; ++j) {
                    unsigned b0,b1,b2,b3;
                    ldsm4(b0,b1,b2,b3, bb + (uint32_t)j * 2048 + bsw[kst]);
                    mma16816(sacc[0][2*j],   a0,a1,a2,a3, b0,b1);
                    mma16816(sacc[0][2*j+1], a0,a1,a2,a3, b2,b3);
                    mma16816(sacc[1][2*j],   a4,a5,a6,a7, b0,b1);
                    mma16816(sacc[1][2*j+1], a4,a5,a6,a7, b2,b3);
                }
            }
            if (lane == 0) MB_ARRIVE(mb_kc + bi * 8);   // this warp consumed bi
            const int gr = gc + 3;
            if (warp == 0 && lane == 0 && gr < ntile * 8) {
                mb_wait(mb_kc + bi * 8, par);           // all 8 warps consumed
                MB_EXPECT_TX(mb_ks + bi * 8, 16384);
                const int t2 = gr >> 3;
                tma2d(su + KS_OFF + bi * 16384, &tmk,
                      (gr & 7) * 64, tile_d(t2), mb_ks + bi * 8);
            }
        }

        // ---- epilogue: kern = 1/(xx+kk-2s+eps) -> bf16 A-frags ----
        // quad-reciprocal: one MUFU rcp per 4 values (1/d from rcp(d0*d1*d2*d3))
        mb_wait(mb_vs, (uint32_t)(tt & 1));           // vs + kk ready
        const float2* kk2 = (const float2*)(smb + KK_OFF);
        unsigned apl[2][8], aph[2][8];
        #pragma unroll
        for (int nt = 0; nt < 8; ++nt) {
            float2 kv = kk2[wd * 32 + nt * 4 + t];
            #pragma unroll
            for (int mh = 0; mh < 2; ++mh) {
                const float xxa = (mh == 0) ? xxe0 : xxe2;
                const float xxb = (mh == 0) ? xxe1 : xxe3;
                float d0v = fmaf(-2.f, sacc[mh][nt][0], xxa + kv.x);
                float d1v = fmaf(-2.f, sacc[mh][nt][1], xxa + kv.y);
                float d2v = fmaf(-2.f, sacc[mh][nt][2], xxb + kv.x);
                float d3v = fmaf(-2.f, sacc[mh][nt][3], xxb + kv.y);
                float p01 = d0v * d1v;
                float p23 = d2v * d3v;
                float rr  = rcpa(p01 * p23);
                float r01 = rr * p23;      // 1/(d0*d1)
                float r23 = rr * p01;      // 1/(d2*d3)
                apl[mh][nt] = packbf(r01 * d1v, r01 * d0v);
                aph[mh][nt] = packbf(r23 * d3v, r23 * d2v);
            }
        }

        // ---- GEMM2: oacc[M32 x 104] += kern[M32 x k64(wd)] @ vT ----
        const uint32_t vb = su + VS_OFF + (uint32_t)wd * 13312;
        #pragma unroll
        for (int k2 = 0; k2 < 4; ++k2) {
            #pragma unroll
            for (int j2 = 0; j2 < 6; ++j2) {
                unsigned b0,b1,b2,b3;
                ldsm4(b0,b1,b2,b3, vb + voff[j2] + vsw[k2]);
                #pragma unroll
                for (int mh = 0; mh < 2; ++mh) {
                    mma16816(oacc[mh][2*j2],   apl[mh][2*k2], aph[mh][2*k2],
                             apl[mh][2*k2+1], aph[mh][2*k2+1], b0, b1);
                    mma16816(oacc[mh][2*j2+1], apl[mh][2*k2], aph[mh][2*k2],
                             apl[mh][2*k2+1], aph[mh][2*k2+1], b2, b3);
                }
            }
            unsigned b0, b1;
            ldsm2(b0, b1, vb + 12288 + v2sw[k2]);
            #pragma unroll
            for (int mh = 0; mh < 2; ++mh)
                mma16816(oacc[mh][12], apl[mh][2*k2], aph[mh][2*k2],
                         apl[mh][2*k2+1], aph[mh][2*k2+1], b0, b1);
        }

        // vs/kk consumed by this warp (no block sync; producer gates refill)
        if (lane == 0) MB_ARRIVE(mb_vc);
        if (warp == 0 && lane == 0 && tt + 1 < ntile) {
            mb_wait(mb_vc, (uint32_t)(tt & 1));       // all 8 warps consumed
            const int dn = tile_d(tt + 1);
            MB_EXPECT_TX(mb_vs, 26624 + 512);
            tma2d(su + VS_OFF,         &tmv, dn,      0, mb_vs);
            tma2d(su + VS_OFF + 13312, &tmv, dn + 64, 0, mb_vs);
            bulk1d(su + KK_OFF, g_kk + dn, 512, mb_vs);
        }
    }

    flush(cur_row);
}

// -------- final reduce over slot partials --------
__global__ void reduce_out(float* __restrict__ out, int N) {
    int i = blockIdx.x * blockDim.x + threadIdx.x;
    if (i >= BTOT * CCOLS) return;
    const int m = i / CCOLS;
    const int c = i - m * CCOLS;
    const int row = m >> 7;
    const int mrow = m & 127;
    const int k0 = cta_of_item(row * ITEMS_PER_ROW, N);
    float s = 0.f;
    int sI = 0;
    while (k0 + sI < N && item_start(k0 + sI, N) < row * ITEMS_PER_ROW + ITEMS_PER_ROW) {
        const float* p = g_part + ((size_t)(row * MAXSLOT + 2 * sI) * BM + mrow) * CP + c;
        s += p[0] + p[(size_t)BM * CP];   // slot 2s and 2s+1 (wd halves)
        ++sI;
    }
    out[i] = s;
}

// -------- host --------
typedef CUresult (*PFN_tmEncode)(CUtensorMap*, CUtensorMapDataType, cuuint32_t,
    void*, const cuuint64_t*, const cuuint64_t*, const cuuint32_t*,
    const cuuint32_t*, CUtensorMapInterleave, CUtensorMapSwizzle,
    CUtensorMapL2promotion, CUtensorMapFloatOOBfill);

#ifndef RTLD_DEFAULT
#define RTLD_DEFAULT ((void*)0)
#endif

extern "C" void kernel_launch(void* const* d_in, const int* in_sizes, int n_in,
                              void* d_out, int out_size) {
    const float* x      = (const float*)d_in[0];   // (4096, 512)
    const float* keys   = (const float*)d_in[1];   // (16384, 512)
    const float* values = (const float*)d_in[2];   // (16384, 100)
    float* out = (float*)d_out;                    // (4096, 100)
    (void)in_sizes; (void)n_in; (void)out_size;

    void *xb_p, *kb_p, *vt_p, *xx_p, *kk_p;
    cudaGetSymbolAddress(&xb_p, g_xb);
    cudaGetSymbolAddress(&kb_p, g_kb);
    cudaGetSymbolAddress(&vt_p, g_vT);
    cudaGetSymbolAddress(&xx_p, g_xx);
    cudaGetSymbolAddress(&kk_p, g_kk);

    // Prologue
    prep_rows<<<BTOT, 128>>>(x, (__nv_bfloat16*)xb_p, (float*)xx_p);
    prep_rows<<<DTOT, 128>>>(keys, (__nv_bfloat16*)kb_p, (float*)kk_p);
    prep_vT<<<DTOT / 128, 256>>>(values);

    // Tensor maps (driver API via dlsym; no -lcuda link dependency)
    void* fn = dlsym(RTLD_DEFAULT, "cuTensorMapEncodeTiled");
    if (!fn) {
        void* h = dlopen("libcuda.so.1", RTLD_NOW | RTLD_GLOBAL);
        if (h) fn = dlsym(h, "cuTensorMapEncodeTiled");
    }
    PFN_tmEncode enc = (PFN_tmEncode)fn;

    CUtensorMap tmx{}, tmk{}, tmv{};
    {
        cuuint64_t dims[2]    = {KTOT, BTOT};
        cuuint64_t strides[1] = {KTOT * 2};
        cuuint32_t box[2]     = {64, 128};
        cuuint32_t es[2]      = {1, 1};
        enc(&tmx, CU_TENSOR_MAP_DATA_TYPE_BFLOAT16, 2, xb_p, dims, strides, box, es,
            CU_TENSOR_MAP_INTERLEAVE_NONE, CU_TENSOR_MAP_SWIZZLE_128B,
            CU_TENSOR_MAP_L2_PROMOTION_L2_128B, CU_TENSOR_MAP_FLOAT_OOB_FILL_NONE);
    }
    {
        cuuint64_t dims[2]    = {KTOT, DTOT};
        cuuint64_t strides[1] = {KTOT * 2};
        cuuint32_t box[2]     = {64, 128};     // one TMA per 16KB ring buffer
        cuuint32_t es[2]      = {1, 1};
        enc(&tmk, CU_TENSOR_MAP_DATA_TYPE_BFLOAT16, 2, kb_p, dims, strides, box, es,
            CU_TENSOR_MAP_INTERLEAVE_NONE, CU_TENSOR_MAP_SWIZZLE_128B,
            CU_TENSOR_MAP_L2_PROMOTION_L2_128B, CU_TENSOR_MAP_FLOAT_OOB_FILL_NONE);
    }
    {
        cuuint64_t dims[2]    = {DTOT, CP};
        cuuint64_t strides[1] = {DTOT * 2};
        cuuint32_t box[2]     = {64, CP};
        cuuint32_t es[2]      = {1, 1};
        enc(&tmv, CU_TENSOR_MAP_DATA_TYPE_BFLOAT16, 2, vt_p, dims, strides, box, es,
            CU_TENSOR_MAP_INTERLEAVE_NONE, CU_TENSOR_MAP_SWIZZLE_128B,
            CU_TENSOR_MAP_L2_PROMOTION_L2_128B, CU_TENSOR_MAP_FLOAT_OOB_FILL_NONE);
    }

    // Persistent grid = #SMs (clamped so row-overlap fits MAXSLOT)
    int dev = 0, nsm = 128;
    cudaGetDevice(&dev);
    cudaDeviceGetAttribute(&nsm, cudaDevAttrMultiProcessorCount, dev);
    int N = nsm > 160 ? 160 : nsm;

    cudaFuncSetAttribute(varkeys_main,
                         cudaFuncAttributeMaxDynamicSharedMemorySize, SMEM_BYTES);
    varkeys_main<<<N, THREADS, SMEM_BYTES>>>(tmx, tmk, tmv);

    reduce_out<<<(BTOT * CCOLS + 255) / 256, 256>>>(out, N);
}